// round 5
// baseline (speedup 1.0000x reference)
#include <cuda_runtime.h>
#include <math.h>

#define BTOT 32768
#define K 64
#define D 64
#define NBLK 128          // main kernel blocks (128 threads, 256 samples each)

typedef unsigned long long ull;

// Precomputed per-component data (scratch: __device__ globals, no allocs)
__device__ float d_M[K][D][D];   // lower triangle of A=Linv^T Linv, diag halved, upper zeroed
__device__ float d_bv[K][D];     // b = A mu
__device__ float d_g[K];         // logw_k - halfLogDet_k - 0.5*D*log(2pi) - 0.5*c_k
__device__ float d_partial[NBLK];

// ---------------- packed f32x2 helpers ----------------
__device__ __forceinline__ ull fma2(ull a, ull b, ull c) {
    ull d;
    asm("fma.rn.f32x2 %0, %1, %2, %3;" : "=l"(d) : "l"(a), "l"(b), "l"(c));
    return d;
}
__device__ __forceinline__ float hadd2(ull a) {
    float lo, hi;
    asm("mov.b64 {%0, %1}, %2;" : "=f"(lo), "=f"(hi) : "l"(a));
    return lo + hi;
}
__device__ __forceinline__ ull pack2(float lo, float hi) {
    ull d;
    asm("mov.b64 %0, {%1, %2};" : "=l"(d) : "f"(lo), "f"(hi));
    return d;
}
__device__ __forceinline__ void lds2(ull& a, ull& b, unsigned addr) {
    asm("ld.shared.v2.b64 {%0, %1}, [%2];" : "=l"(a), "=l"(b) : "r"(addr));
}
__device__ __forceinline__ void cp16(unsigned saddr, const void* gaddr) {
    asm volatile("cp.async.cg.shared.global [%0], [%1], 16;" :: "r"(saddr), "l"(gaddr));
}
#define CP_COMMIT()  asm volatile("cp.async.commit_group;" ::: "memory")
#define CP_WAIT1()   asm volatile("cp.async.wait_group 1;" ::: "memory")

// ---------------------------------------------------------------------------
// Prep: per component k (one block of 64 threads).
//   Thread j computes column j of Linv ENTIRELY IN REGISTERS via forward
//   substitution with fully static bounds (terms with m<j are exact 0*0).
//   Linv stored transposed so A = Linv^T Linv becomes row-dot-row (f32x2).
// ---------------------------------------------------------------------------
__global__ __launch_bounds__(64) void prep_kernel(const float* __restrict__ scale_raw,
                            const float* __restrict__ means_raw,
                            const float* __restrict__ weights_raw) {
    const int k = blockIdx.x;
    const int j = threadIdx.x;          // 64 threads

    __shared__ float Ls[D][D];          // L rows (float4-aligned); later reused for A
    __shared__ float Vt[D][D];          // Vt[p][i] = Linv[i][p]
    __shared__ float rdiag[D];
    __shared__ float ms[D];
    __shared__ float pdiag[D];
    __shared__ float prodsh[D];

    const float sc2 = 1.0f / 512.0f;    // 1/sqrt(K*D*D)
    const float sc1 = 1.0f / 64.0f;     // 1/sqrt(K*D)

    // Load L (thread j handles column j of every row; coalesced over j).
    // Upper triangle is exact 0 — required by the static-bound recurrence.
    for (int i = 0; i < D; ++i) {
        float p = scale_raw[((size_t)k * D + i) * D + j] * sc2;
        float v;
        if (j < i)       v = p;
        else if (j == i) { float e = expf(p); v = e; pdiag[i] = p; rdiag[i] = 1.0f / e; }
        else             v = 0.0f;
        Ls[i][j] = v;
    }
    ms[j] = means_raw[k * D + j] * sc1;
    __syncthreads();

    // Forward substitution, column j in registers. Static bounds: for m<j the
    // product L[i][m] (could be nonzero) * v[m] (exact 0) vanishes; for i<j
    // delta=0 and all terms 0 -> v[i]=0 exactly.
    float v[D];
    #pragma unroll
    for (int i = 0; i < D; ++i) {
        float a0 = 0.f, a1 = 0.f, a2 = 0.f, a3 = 0.f;
        #pragma unroll
        for (int m = 0; m < i; m += 4) {
            a0 = fmaf(Ls[i][m + 0], v[m + 0], a0);
            if (m + 1 < i) a1 = fmaf(Ls[i][m + 1], v[m + 1], a1);
            if (m + 2 < i) a2 = fmaf(Ls[i][m + 2], v[m + 2], a2);
            if (m + 3 < i) a3 = fmaf(Ls[i][m + 3], v[m + 3], a3);
        }
        float de = (j == i) ? 1.0f : 0.0f;
        v[i] = (de - ((a0 + a1) + (a2 + a3))) * rdiag[i];
    }
    // Store transposed: thread j writes contiguous row j of Vt.
    #pragma unroll
    for (int i = 0; i < D; i += 4) {
        ((float4*)&Vt[j][0])[i >> 2] = make_float4(v[i], v[i + 1], v[i + 2], v[i + 3]);
    }
    __syncthreads();

    // Pack v for f32x2 dots.
    ull vp[D / 2];
    #pragma unroll
    for (int i = 0; i < D / 2; ++i) vp[i] = pack2(v[2 * i], v[2 * i + 1]);

    // A row j: A[j][q] = dot(v, Vt[q][:]) ; fold b and masked-M store.
    float bj = 0.0f;
    const unsigned vtbase = (unsigned)__cvta_generic_to_shared(&Vt[0][0]);
    #pragma unroll 4
    for (int q = 0; q < D; ++q) {
        ull acc = 0ULL;
        const unsigned qa = vtbase + (unsigned)q * 256u;
        #pragma unroll
        for (int c = 0; c < 16; ++c) {
            ull w0, w1;
            lds2(w0, w1, qa + 16u * c);
            acc = fma2(w0, vp[2 * c + 0], acc);
            acc = fma2(w1, vp[2 * c + 1], acc);
        }
        float a = hadd2(acc);
        bj = fmaf(a, ms[q], bj);
        Ls[j][q] = (q < j) ? a : ((q == j) ? 0.5f * a : 0.0f);  // masked M row
    }
    d_bv[k][j] = bj;
    prodsh[j] = ms[j] * bj;
    __syncthreads();

    // Coalesced store of M (Ls layout == d_M[k] layout).
    {
        const float4* src = (const float4*)&Ls[0][0];
        float4* dst = (float4*)&d_M[k][0][0];
        #pragma unroll
        for (int idx = 0; idx < 16; ++idx) dst[j + 64 * idx] = src[j + 64 * idx];
    }

    if (j == 0) {
        float hld = 0.0f, c = 0.0f;
        for (int i = 0; i < D; ++i) { hld += pdiag[i]; c += prodsh[i]; }
        const float s3 = 0.125f;   // 1/sqrt(K)
        float wmax = -1e30f;
        for (int q = 0; q < K; ++q) wmax = fmaxf(wmax, weights_raw[q] * s3);
        float lse = 0.0f;
        for (int q = 0; q < K; ++q) lse += expf(weights_raw[q] * s3 - wmax);
        float logwk = weights_raw[k] * s3 - (wmax + logf(lse));
        const float HALF_D_LOG2PI = 0.5f * 64.0f * 1.8378770664093453f;
        d_g[k] = logwk - hld - HALF_D_LOG2PI - 0.5f * c;
    }
}

// ---------------------------------------------------------------------------
// Main: 2 samples per thread (128 blocks x 128 threads x 2 = 32768, one
// balanced wave). val = b.x - x^T M x + g (maha = 2*quad). cp.async staging.
// ---------------------------------------------------------------------------
__global__ __launch_bounds__(128) void gmm_main(const float* __restrict__ x) {
    __shared__ float4 Ms[2][D * D / 4];   // 2 x 16 KB
    __shared__ float4 Bsh[2][D / 4];
    __shared__ float  gs[K];
    __shared__ float  red[128];

    const int tid = threadIdx.x;
    const size_t bA = (size_t)blockIdx.x * 256 + tid;
    const size_t bB = bA + 128;

    // all component constants g once
    if (tid < K) gs[tid] = d_g[tid];

    // two sample rows, packed into f32x2 pairs
    ull xa[32], xb[32];
    {
        const float4* pa = (const float4*)(x + bA * D);
        const float4* pb = (const float4*)(x + bB * D);
        #pragma unroll
        for (int i = 0; i < 16; ++i) {
            float4 v = pa[i];
            xa[2 * i + 0] = pack2(v.x, v.y);
            xa[2 * i + 1] = pack2(v.z, v.w);
        }
        #pragma unroll
        for (int i = 0; i < 16; ++i) {
            float4 v = pb[i];
            xb[2 * i + 0] = pack2(v.x, v.y);
            xb[2 * i + 1] = pack2(v.z, v.w);
        }
    }

    // async-copy helpers: M tile 16KB -> 128B/thread (8x16B); b: threads 0-15
    const float4* Mg0 = (const float4*)&d_M[0][0][0];
    {
        unsigned ds = (unsigned)__cvta_generic_to_shared(&Ms[0][0]);
        #pragma unroll
        for (int r = 0; r < 8; ++r)
            cp16(ds + 16u * (unsigned)(tid + 128 * r), Mg0 + tid + 128 * r);
        if (tid < 16)
            cp16((unsigned)__cvta_generic_to_shared(&Bsh[0][0]) + 16u * tid,
                 ((const float4*)&d_bv[0][0]) + tid);
        CP_COMMIT();
    }

    float mmaxA = -1e30f, ssumA = 0.0f;
    float mmaxB = -1e30f, ssumB = 0.0f;

    for (int k = 0; k < K; ++k) {
        const int cur = k & 1, nxt = cur ^ 1;

        // issue copy of next component into the other buffer
        {
            const int kn = (k + 1 < K) ? k + 1 : K - 1;
            const float4* Mg = (const float4*)&d_M[kn][0][0];
            unsigned ds = (unsigned)__cvta_generic_to_shared(&Ms[nxt][0]);
            #pragma unroll
            for (int r = 0; r < 8; ++r)
                cp16(ds + 16u * (unsigned)(tid + 128 * r), Mg + tid + 128 * r);
            if (tid < 16)
                cp16((unsigned)__cvta_generic_to_shared(&Bsh[nxt][0]) + 16u * tid,
                     ((const float4*)&d_bv[kn][0]) + tid);
            CP_COMMIT();
        }
        CP_WAIT1();          // cur buffer complete (newest group may still fly)
        __syncthreads();

        const unsigned mbase = (unsigned)__cvta_generic_to_shared(&Ms[cur][0]);
        const unsigned bbase = (unsigned)__cvta_generic_to_shared(&Bsh[cur][0]);

        ull qaccA = 0ULL, baccA = 0ULL;
        ull qaccB = 0ULL, baccB = 0ULL;

        // rows 4t..4t+3 need exactly t+1 float4 chunks (padding is exact 0)
        #pragma unroll
        for (int t = 0; t < 16; ++t) {
            ull a0A = 0ULL, a1A = 0ULL, a2A = 0ULL, a3A = 0ULL;
            ull a0B = 0ULL, a1B = 0ULL, a2B = 0ULL, a3B = 0ULL;
            const unsigned ra = mbase + (unsigned)t * 1024u;   // row 4t (256 B/row)
            #pragma unroll
            for (int c = 0; c <= t; ++c) {
                ull m0a, m0b, m1a, m1b, m2a, m2b, m3a, m3b;
                lds2(m0a, m0b, ra + 16u * c);
                lds2(m1a, m1b, ra + 256u + 16u * c);
                lds2(m2a, m2b, ra + 512u + 16u * c);
                lds2(m3a, m3b, ra + 768u + 16u * c);
                const ull xloA = xa[2 * c], xhiA = xa[2 * c + 1];
                const ull xloB = xb[2 * c], xhiB = xb[2 * c + 1];
                a0A = fma2(m0a, xloA, a0A); a0A = fma2(m0b, xhiA, a0A);
                a1A = fma2(m1a, xloA, a1A); a1A = fma2(m1b, xhiA, a1A);
                a2A = fma2(m2a, xloA, a2A); a2A = fma2(m2b, xhiA, a2A);
                a3A = fma2(m3a, xloA, a3A); a3A = fma2(m3b, xhiA, a3A);
                a0B = fma2(m0a, xloB, a0B); a0B = fma2(m0b, xhiB, a0B);
                a1B = fma2(m1a, xloB, a1B); a1B = fma2(m1b, xhiB, a1B);
                a2B = fma2(m2a, xloB, a2B); a2B = fma2(m2b, xhiB, a2B);
                a3B = fma2(m3a, xloB, a3B); a3B = fma2(m3b, xhiB, a3B);
            }
            qaccA = fma2(xa[2 * t + 0], pack2(hadd2(a0A), hadd2(a1A)), qaccA);
            qaccA = fma2(xa[2 * t + 1], pack2(hadd2(a2A), hadd2(a3A)), qaccA);
            qaccB = fma2(xb[2 * t + 0], pack2(hadd2(a0B), hadd2(a1B)), qaccB);
            qaccB = fma2(xb[2 * t + 1], pack2(hadd2(a2B), hadd2(a3B)), qaccB);
            ull b01, b23;
            lds2(b01, b23, bbase + 16u * t);
            baccA = fma2(b01, xa[2 * t + 0], baccA);
            baccA = fma2(b23, xa[2 * t + 1], baccA);
            baccB = fma2(b01, xb[2 * t + 0], baccB);
            baccB = fma2(b23, xb[2 * t + 1], baccB);
        }

        const float gk = gs[k];
        const float valA = hadd2(baccA) - hadd2(qaccA) + gk;
        const float valB = hadd2(baccB) - hadd2(qaccB) + gk;

        // online logsumexp (per sample)
        if (valA > mmaxA) { ssumA = ssumA * expf(mmaxA - valA) + 1.0f; mmaxA = valA; }
        else              { ssumA += expf(valA - mmaxA); }
        if (valB > mmaxB) { ssumB = ssumB * expf(mmaxB - valB) + 1.0f; mmaxB = valB; }
        else              { ssumB += expf(valB - mmaxB); }

        __syncthreads();    // all warps done with cur before next iter overwrites it
    }

    float lp = (mmaxA + logf(ssumA)) + (mmaxB + logf(ssumB));

    // deterministic block reduction
    red[tid] = lp;
    __syncthreads();
    #pragma unroll
    for (int s = 64; s > 0; s >>= 1) {
        if (tid < s) red[tid] += red[tid + s];
        __syncthreads();
    }
    if (tid == 0) d_partial[blockIdx.x] = red[0];
}

__global__ void finish_kernel(float* __restrict__ out) {
    __shared__ float red[NBLK];
    int tid = threadIdx.x;
    red[tid] = d_partial[tid];
    __syncthreads();
    #pragma unroll
    for (int s = NBLK / 2; s > 0; s >>= 1) {
        if (tid < s) red[tid] += red[tid + s];
        __syncthreads();
    }
    if (tid == 0) out[0] = -red[0] / (float)BTOT;
}

extern "C" void kernel_launch(void* const* d_in, const int* in_sizes, int n_in,
                              void* d_out, int out_size) {
    const float* x      = (const float*)d_in[0];
    const float* means  = (const float*)d_in[1];
    const float* scale  = (const float*)d_in[2];
    const float* wraw   = (const float*)d_in[3];

    prep_kernel<<<K, D>>>(scale, means, wraw);
    gmm_main<<<NBLK, 128>>>(x);
    finish_kernel<<<1, NBLK>>>((float*)d_out);
}

// round 6
// speedup vs baseline: 1.0648x; 1.0648x over previous
#include <cuda_runtime.h>
#include <math.h>

#define BTOT 32768
#define K 64
#define D 64
#define NMERGE 256        // merge kernel blocks

typedef unsigned long long ull;

// Precomputed per-component data (scratch: __device__ globals, no allocs)
__device__ float d_M[K][D][D];   // lower triangle of A=Linv^T Linv, diag halved, upper zeroed
__device__ float d_bv[K][D];     // b = A mu
__device__ float d_g[K];         // logw_k - halfLogDet_k - 0.5*D*log(2pi) - 0.5*c_k
__device__ float d_mm[2][BTOT];  // per-half running max
__device__ float d_ss[2][BTOT];  // per-half running sum
__device__ float d_partial[NMERGE];

// ---------------- packed f32x2 helpers ----------------
__device__ __forceinline__ ull fma2(ull a, ull b, ull c) {
    ull d;
    asm("fma.rn.f32x2 %0, %1, %2, %3;" : "=l"(d) : "l"(a), "l"(b), "l"(c));
    return d;
}
__device__ __forceinline__ float hadd2(ull a) {
    float lo, hi;
    asm("mov.b64 {%0, %1}, %2;" : "=f"(lo), "=f"(hi) : "l"(a));
    return lo + hi;
}
__device__ __forceinline__ ull pack2(float lo, float hi) {
    ull d;
    asm("mov.b64 %0, {%1, %2};" : "=l"(d) : "f"(lo), "f"(hi));
    return d;
}
__device__ __forceinline__ void lds2(ull& a, ull& b, unsigned addr) {
    asm("ld.shared.v2.b64 {%0, %1}, [%2];" : "=l"(a), "=l"(b) : "r"(addr));
}
__device__ __forceinline__ void cp16(unsigned saddr, const void* gaddr) {
    asm volatile("cp.async.cg.shared.global [%0], [%1], 16;" :: "r"(saddr), "l"(gaddr));
}
#define CP_COMMIT()  asm volatile("cp.async.commit_group;" ::: "memory")
#define CP_WAIT1()   asm volatile("cp.async.wait_group 1;" ::: "memory")

// ---------------------------------------------------------------------------
// Prep: one block of 64 threads per component k. Thread j owns column j of
// Linv; recurrence runs through smem (conflict-free, zero barriers, uniform
// bounds), with the previous value carried in a register to dodge the
// STS->LDS no-store-forward hazard. Small code body (rolled loops).
// ---------------------------------------------------------------------------
__global__ __launch_bounds__(64) void prep_kernel(const float* __restrict__ scale_raw,
                            const float* __restrict__ means_raw,
                            const float* __restrict__ weights_raw) {
    const int k = blockIdx.x;
    const int j = threadIdx.x;          // 64 threads

    __shared__ float Ls[D][D];          // L rows; later overwritten with masked M rows
    __shared__ float Vs[D][D];          // Vs[i][j] = Linv[i][j]
    __shared__ float rdiag[D];
    __shared__ float ms[D];
    __shared__ float pdiag[D];
    __shared__ float prodsh[D];

    const float sc2 = 1.0f / 512.0f;    // 1/sqrt(K*D*D)
    const float sc1 = 1.0f / 64.0f;     // 1/sqrt(K*D)

    // Load L (coalesced over j). Upper triangle exact 0.
    #pragma unroll 4
    for (int i = 0; i < D; ++i) {
        float p = scale_raw[((size_t)k * D + i) * D + j] * sc2;
        float v;
        if (j < i)       v = p;
        else if (j == i) { float e = expf(p); v = e; pdiag[i] = p; rdiag[i] = 1.0f / e; }
        else             v = 0.0f;
        Ls[i][j] = v;
    }
    ms[j] = means_raw[k * D + j] * sc1;
    __syncthreads();

    // Forward substitution, column j. Uniform bounds for all threads:
    // terms with m<j multiply exact zeros. No barriers (column-private).
    float prev = 0.0f;   // Vs[i-1][j]
    #pragma unroll 1
    for (int i = 0; i < D; ++i) {
        const float* Lrow = &Ls[i][0];
        const int e = i - 1;                // m = e handled via 'prev'
        const int mend = (e > 0) ? (e & ~3) : 0;
        float a0 = 0.f, a1 = 0.f, a2 = 0.f, a3 = 0.f;
        #pragma unroll 1
        for (int m = 0; m < mend; m += 4) {
            a0 = fmaf(Lrow[m + 0], Vs[m + 0][j], a0);
            a1 = fmaf(Lrow[m + 1], Vs[m + 1][j], a1);
            a2 = fmaf(Lrow[m + 2], Vs[m + 2][j], a2);
            a3 = fmaf(Lrow[m + 3], Vs[m + 3][j], a3);
        }
        for (int m = mend; m < e; ++m) a0 = fmaf(Lrow[m], Vs[m][j], a0);
        float s = (a0 + a1) + (a2 + a3);
        if (i > 0) s = fmaf(Lrow[e], prev, s);
        float de = (j == i) ? 1.0f : 0.0f;
        float vi = (de - s) * rdiag[i];
        Vs[i][j] = vi;
        prev = vi;
    }
    __syncthreads();

    // Own column into registers (static indexing only — no local spill)
    float v[D];
    #pragma unroll
    for (int i = 0; i < D; ++i) v[i] = Vs[i][j];

    // A row j: A[j][q] = dot(col_j, col_q); fold b; write masked M row into Ls.
    float bj = 0.0f;
    #pragma unroll 2
    for (int q = 0; q < D; ++q) {
        float a0 = 0.f, a1 = 0.f, a2 = 0.f, a3 = 0.f;
        #pragma unroll
        for (int i = 0; i < D; i += 4) {
            a0 = fmaf(v[i + 0], Vs[i + 0][q], a0);   // Vs[i][q] broadcast
            a1 = fmaf(v[i + 1], Vs[i + 1][q], a1);
            a2 = fmaf(v[i + 2], Vs[i + 2][q], a2);
            a3 = fmaf(v[i + 3], Vs[i + 3][q], a3);
        }
        float a = (a0 + a1) + (a2 + a3);
        bj = fmaf(a, ms[q], bj);
        Ls[j][q] = (q < j) ? a : ((q == j) ? 0.5f * a : 0.0f);
    }
    d_bv[k][j] = bj;
    prodsh[j] = ms[j] * bj;
    __syncthreads();

    // Coalesced store of M (Ls layout == d_M[k] layout).
    {
        const float4* src = (const float4*)&Ls[0][0];
        float4* dst = (float4*)&d_M[k][0][0];
        #pragma unroll
        for (int idx = 0; idx < 16; ++idx) dst[j + 64 * idx] = src[j + 64 * idx];
    }

    if (j == 0) {
        float hld = 0.0f, c = 0.0f;
        for (int i = 0; i < D; ++i) { hld += pdiag[i]; c += prodsh[i]; }
        const float s3 = 0.125f;   // 1/sqrt(K)
        float wmax = -1e30f;
        for (int q = 0; q < K; ++q) wmax = fmaxf(wmax, weights_raw[q] * s3);
        float lse = 0.0f;
        for (int q = 0; q < K; ++q) lse += expf(weights_raw[q] * s3 - wmax);
        float logwk = weights_raw[k] * s3 - (wmax + logf(lse));
        const float HALF_D_LOG2PI = 0.5f * 64.0f * 1.8378770664093453f;
        d_g[k] = logwk - hld - HALF_D_LOG2PI - 0.5f * c;
    }
}

// ---------------------------------------------------------------------------
// Main: split-K. Grid 512 = 256 sample-groups x 2 component-halves.
// Block (g,h): samples g*128..g*128+127, components [32h, 32h+32).
// 1 sample/thread, f32x2 FMAs, cp.async double-buffered tiles.
// Emits per-sample (mmax, ssum) for its half.
// ---------------------------------------------------------------------------
__global__ __launch_bounds__(128) void gmm_main(const float* __restrict__ x) {
    __shared__ float4 Ms[2][D * D / 4];   // 2 x 16 KB
    __shared__ float4 Bsh[2][D / 4];
    __shared__ float  gs[32];

    const int tid = threadIdx.x;
    const int g = blockIdx.x >> 1;
    const int h = blockIdx.x & 1;
    const int k0 = h << 5;
    const size_t b = (size_t)g * 128 + tid;

    if (tid < 32) gs[tid] = d_g[k0 + tid];

    // sample row, packed into f32x2 pairs
    ull xp2[32];
    {
        const float4* xp = (const float4*)(x + b * D);
        #pragma unroll
        for (int i = 0; i < 16; ++i) {
            float4 v = xp[i];
            xp2[2 * i + 0] = pack2(v.x, v.y);
            xp2[2 * i + 1] = pack2(v.z, v.w);
        }
    }

    // initial async load of k0 tile into buffer 0
    {
        const float4* Mg = (const float4*)&d_M[k0][0][0];
        unsigned ds = (unsigned)__cvta_generic_to_shared(&Ms[0][0]);
        #pragma unroll
        for (int r = 0; r < 8; ++r)
            cp16(ds + 16u * (unsigned)(tid + 128 * r), Mg + tid + 128 * r);
        if (tid < 16)
            cp16((unsigned)__cvta_generic_to_shared(&Bsh[0][0]) + 16u * tid,
                 ((const float4*)&d_bv[k0][0]) + tid);
        CP_COMMIT();
    }

    float mmax = -1e30f, ssum = 0.0f;

    for (int kk = 0; kk < 32; ++kk) {
        const int cur = kk & 1, nxt = cur ^ 1;

        // issue copy of next component into the other buffer
        {
            const int kn = k0 + ((kk + 1 < 32) ? kk + 1 : 31);
            const float4* Mg = (const float4*)&d_M[kn][0][0];
            unsigned ds = (unsigned)__cvta_generic_to_shared(&Ms[nxt][0]);
            #pragma unroll
            for (int r = 0; r < 8; ++r)
                cp16(ds + 16u * (unsigned)(tid + 128 * r), Mg + tid + 128 * r);
            if (tid < 16)
                cp16((unsigned)__cvta_generic_to_shared(&Bsh[nxt][0]) + 16u * tid,
                     ((const float4*)&d_bv[kn][0]) + tid);
            CP_COMMIT();
        }
        CP_WAIT1();          // cur buffer's group complete (own thread)
        __syncthreads();     // all threads' copies of cur landed

        const unsigned mbase = (unsigned)__cvta_generic_to_shared(&Ms[cur][0]);
        const unsigned bbase = (unsigned)__cvta_generic_to_shared(&Bsh[cur][0]);

        ull qacc = 0ULL, bacc = 0ULL;

        // rows 4t..4t+3 need exactly t+1 float4 chunks (padding is exact 0)
        #pragma unroll
        for (int t = 0; t < 16; ++t) {
            ull a0 = 0ULL, a1 = 0ULL, a2 = 0ULL, a3 = 0ULL;
            const unsigned ra = mbase + (unsigned)t * 1024u;   // row 4t (256 B/row)
            #pragma unroll
            for (int c = 0; c <= t; ++c) {
                ull m0a, m0b, m1a, m1b, m2a, m2b, m3a, m3b;
                lds2(m0a, m0b, ra + 16u * c);
                lds2(m1a, m1b, ra + 256u + 16u * c);
                lds2(m2a, m2b, ra + 512u + 16u * c);
                lds2(m3a, m3b, ra + 768u + 16u * c);
                const ull xlo = xp2[2 * c], xhi = xp2[2 * c + 1];
                a0 = fma2(m0a, xlo, a0); a0 = fma2(m0b, xhi, a0);
                a1 = fma2(m1a, xlo, a1); a1 = fma2(m1b, xhi, a1);
                a2 = fma2(m2a, xlo, a2); a2 = fma2(m2b, xhi, a2);
                a3 = fma2(m3a, xlo, a3); a3 = fma2(m3b, xhi, a3);
            }
            qacc = fma2(xp2[2 * t + 0], pack2(hadd2(a0), hadd2(a1)), qacc);
            qacc = fma2(xp2[2 * t + 1], pack2(hadd2(a2), hadd2(a3)), qacc);
            ull b01, b23;
            lds2(b01, b23, bbase + 16u * t);
            bacc = fma2(b01, xp2[2 * t + 0], bacc);
            bacc = fma2(b23, xp2[2 * t + 1], bacc);
        }

        const float val = hadd2(bacc) - hadd2(qacc) + gs[kk];

        // branchless online logsumexp
        const float mn = fmaxf(mmax, val);
        ssum = ssum * __expf(mmax - mn) + __expf(val - mn);
        mmax = mn;

        __syncthreads();    // all warps done with cur before it is overwritten
    }

    d_mm[h][b] = mmax;
    d_ss[h][b] = ssum;
}

// ---------------------------------------------------------------------------
// Merge halves (exact logsumexp merge) + deterministic partial sums.
// ---------------------------------------------------------------------------
__global__ __launch_bounds__(128) void merge_kernel() {
    __shared__ float red[128];
    const int tid = threadIdx.x;
    const size_t b = (size_t)blockIdx.x * 128 + tid;

    float m0 = d_mm[0][b], s0 = d_ss[0][b];
    float m1 = d_mm[1][b], s1 = d_ss[1][b];
    float m = fmaxf(m0, m1);
    float lp = m + logf(fmaf(s0, expf(m0 - m), s1 * expf(m1 - m)));

    red[tid] = lp;
    __syncthreads();
    #pragma unroll
    for (int s = 64; s > 0; s >>= 1) {
        if (tid < s) red[tid] += red[tid + s];
        __syncthreads();
    }
    if (tid == 0) d_partial[blockIdx.x] = red[0];
}

__global__ void finish_kernel(float* __restrict__ out) {
    __shared__ float red[NMERGE];
    int tid = threadIdx.x;
    red[tid] = d_partial[tid];
    __syncthreads();
    #pragma unroll
    for (int s = NMERGE / 2; s > 0; s >>= 1) {
        if (tid < s) red[tid] += red[tid + s];
        __syncthreads();
    }
    if (tid == 0) out[0] = -red[0] / (float)BTOT;
}

extern "C" void kernel_launch(void* const* d_in, const int* in_sizes, int n_in,
                              void* d_out, int out_size) {
    const float* x      = (const float*)d_in[0];
    const float* means  = (const float*)d_in[1];
    const float* scale  = (const float*)d_in[2];
    const float* wraw   = (const float*)d_in[3];

    prep_kernel<<<K, D>>>(scale, means, wraw);
    gmm_main<<<512, 128>>>(x);
    merge_kernel<<<NMERGE, 128>>>();
    finish_kernel<<<1, NMERGE>>>((float*)d_out);
}

// round 10
// speedup vs baseline: 2.4771x; 2.3263x over previous
#include <cuda_runtime.h>
#include <cuda_bf16.h>
#include <math.h>

#define BTOT 32768
#define K 64
#define D 64
#define NF 2176            // padded feature count (136 k-steps of 16)
#define NREAL 2144         // 64 linear + 2080 lower-tri pairs
#define NKS 136
#define NBLK_MAIN 256      // 128 samples per CTA

typedef unsigned long long ull;

// ---------------- device scratch (no allocs) ----------------
// B operand in mma.sync fragment-linear layout:
// entry e = (kstep*8 + ntile)*32 + lane, 8 bytes = {b0(lo32), b1(hi32)}
__device__ ull   d_Wf[NKS * 8 * 32];
__device__ float d_g[K];
__device__ int   d_tab[NF];             // (i<<8)|j feature index pairs
__device__ float d_partial[NBLK_MAIN];

// ---------------- helpers ----------------
__device__ __forceinline__ ull fma2(ull a, ull b, ull c) {
    ull d; asm("fma.rn.f32x2 %0, %1, %2, %3;" : "=l"(d) : "l"(a), "l"(b), "l"(c)); return d;
}
__device__ __forceinline__ float hadd2(ull a) {
    float lo, hi; asm("mov.b64 {%0, %1}, %2;" : "=f"(lo), "=f"(hi) : "l"(a)); return lo + hi;
}
__device__ __forceinline__ ull pack2(float lo, float hi) {
    ull d; asm("mov.b64 %0, {%1, %2};" : "=l"(d) : "f"(lo), "f"(hi)); return d;
}
__device__ __forceinline__ void lds2(ull& a, ull& b, unsigned addr) {
    asm("ld.shared.v2.b64 {%0, %1}, [%2];" : "=l"(a), "=l"(b) : "r"(addr));
}
// packs: lower 16 bits <- lo, upper <- hi (first PTX src goes to upper half)
__device__ __forceinline__ unsigned cvt_bf16x2(float lo, float hi) {
    unsigned r;
    asm("cvt.rn.satfinite.bf16x2.f32 %0, %1, %2;" : "=r"(r) : "f"(hi), "f"(lo));
    return r;
}
__device__ __forceinline__ void mma_bf16(float& c0, float& c1, float& c2, float& c3,
                                         unsigned a0, unsigned a1, unsigned a2, unsigned a3,
                                         unsigned b0, unsigned b1) {
    asm volatile("mma.sync.aligned.m16n8k16.row.col.f32.bf16.bf16.f32 "
                 "{%0,%1,%2,%3}, {%4,%5,%6,%7}, {%8,%9}, {%0,%1,%2,%3};"
                 : "+f"(c0), "+f"(c1), "+f"(c2), "+f"(c3)
                 : "r"(a0), "r"(a1), "r"(a2), "r"(a3), "r"(b0), "r"(b1));
}

// ---------------------------------------------------------------------------
// init_tables: feature f -> (i,j). f<64: (f,64) linear (x[64]=1). 64..2143:
// lower-tri pairs (j<=i) row-major. pad: (65,65) (x[65]=0).
// ---------------------------------------------------------------------------
__global__ void init_tables() {
    for (int f = threadIdx.x; f < NF; f += blockDim.x) {
        int i, j;
        if (f < 64) { i = f; j = 64; }
        else if (f < NREAL) {
            int p = f - 64;
            int ii = (int)((sqrtf(8.0f * p + 1.0f) - 1.0f) * 0.5f);
            while ((ii + 1) * (ii + 2) / 2 <= p) ++ii;
            while (ii * (ii + 1) / 2 > p) --ii;
            i = ii; j = p - ii * (ii + 1) / 2;
        } else { i = 65; j = 65; }
        d_tab[f] = (i << 8) | j;
    }
}

// ---------------------------------------------------------------------------
// prep: one 128-thread block per component k.
//   L -> Linv (forward substitution), A = Linv^T Linv, b = A mu, g.
//   Weights written to d_Wf in mma.sync B-fragment layout (bf16).
// ---------------------------------------------------------------------------
__global__ __launch_bounds__(128) void prep_kernel(const float* __restrict__ scale_raw,
                                                   const float* __restrict__ means_raw,
                                                   const float* __restrict__ weights_raw) {
    const int k = blockIdx.x;
    const int tid = threadIdx.x;

    __shared__ float Ls[D][D];     // L; later holds A
    __shared__ float VT[D][68];    // VT[j][i] = Linv[i][j] (16B-aligned stride)
    __shared__ float rdiag[D], ms[D], pdiag[D], bsm[D], wsh[D];
    __shared__ float wstage[K];
    __shared__ float bp2[128];

    const float sc2 = 1.0f / 512.0f;
    const float sc1 = 1.0f / 64.0f;

    for (int idx = tid; idx < D * D; idx += 128) {
        int i = idx >> 6, jj = idx & 63;
        float p = scale_raw[(size_t)k * D * D + idx] * sc2;
        float v;
        if (jj < i) v = p;
        else if (jj == i) { float e = expf(p); v = e; pdiag[i] = p; rdiag[i] = 1.0f / e; }
        else v = 0.0f;
        Ls[i][jj] = v;
    }
    if (tid < D) ms[tid] = means_raw[k * D + tid] * sc1;
    if (tid < K) wstage[tid] = weights_raw[tid] * 0.125f;
    __syncthreads();

    // forward substitution: thread j (<64) computes column j into VT[j][*]
    if (tid < D) {
        const int j = tid;
        float prev = 0.0f;
        #pragma unroll 1
        for (int i = 0; i < D; ++i) {
            const float* Lrow = &Ls[i][0];
            const int e = i - 1;
            const int mend = (e > 0) ? (e & ~3) : 0;
            float a0 = 0.f, a1 = 0.f, a2 = 0.f, a3 = 0.f;
            #pragma unroll 1
            for (int m = 0; m < mend; m += 4) {
                float4 vm = *(const float4*)&VT[j][m];
                a0 = fmaf(Lrow[m + 0], vm.x, a0);
                a1 = fmaf(Lrow[m + 1], vm.y, a1);
                a2 = fmaf(Lrow[m + 2], vm.z, a2);
                a3 = fmaf(Lrow[m + 3], vm.w, a3);
            }
            for (int m = mend; m < e; ++m) a0 = fmaf(Lrow[m], VT[j][m], a0);
            float s = (a0 + a1) + (a2 + a3);
            if (i > 0) s = fmaf(Lrow[e], prev, s);
            float de = (j == i) ? 1.0f : 0.0f;
            float vi = (de - s) * rdiag[i];
            VT[j][i] = vi;
            prev = vi;
        }
    }
    __syncthreads();

    // A rows: thread (jj, h): A[jj][q] for q in [32h, 32h+32)
    const int jj = tid & 63, h = tid >> 6;
    ull vp[32];
    {
        const float4* myrow = (const float4*)&VT[jj][0];
        #pragma unroll
        for (int c = 0; c < 16; ++c) {
            float4 v4 = myrow[c];
            vp[2 * c + 0] = pack2(v4.x, v4.y);
            vp[2 * c + 1] = pack2(v4.z, v4.w);
        }
    }
    float bpart = 0.0f;
    const unsigned vtb = (unsigned)__cvta_generic_to_shared(&VT[0][0]);
    #pragma unroll 2
    for (int qq = 0; qq < 32; ++qq) {
        const int q = h * 32 + qq;
        const unsigned qa = vtb + (unsigned)q * 272u;
        ull acc = 0ULL;
        #pragma unroll
        for (int c = 0; c < 16; ++c) {
            ull w0, w1;
            lds2(w0, w1, qa + 16u * c);
            acc = fma2(w0, vp[2 * c + 0], acc);
            acc = fma2(w1, vp[2 * c + 1], acc);
        }
        float a = hadd2(acc);
        Ls[jj][q] = a;                       // overwrite L with A
        bpart = fmaf(a, ms[q], bpart);
    }
    bp2[tid] = bpart;
    __syncthreads();
    if (tid < D) {
        float bj = bp2[tid] + bp2[tid + 64];
        bsm[tid] = bj;
        wsh[tid] = ms[tid] * bj;             // mu_j * b_j
    }
    __syncthreads();

    if (tid == 0) {
        float hld = 0.0f, c = 0.0f;
        for (int i = 0; i < D; ++i) { hld += pdiag[i]; c += wsh[i]; }
        float wmax = -1e30f;
        for (int q = 0; q < K; ++q) wmax = fmaxf(wmax, wstage[q]);
        float lse = 0.0f;
        for (int q = 0; q < K; ++q) lse += expf(wstage[q] - wmax);
        float logwk = wstage[k] - (wmax + logf(lse));
        const float HALF_D_LOG2PI = 0.5f * 64.0f * 1.8378770664093453f;
        d_g[k] = logwk - hld - HALF_D_LOG2PI - 0.5f * c;
    }

    // W scatter into B-fragment layout: entry e = (ks*8 + k/8)*32 + lane,
    // lane = 4*(k%8) + (within%8)/2; bf16 slot = (within/8)*2 + (within&1).
    for (int f = tid; f < NF; f += 128) {
        int tb = d_tab[f];
        int i = tb >> 8, j3 = tb & 255;
        float w;
        if (j3 == 64)      w = bsm[i];                       // linear: b
        else if (j3 == 65) w = 0.0f;                          // pad
        else if (i == j3)  w = -0.5f * (Ls[i][i] - 1.0f);     // -0.5*E_diag
        else               w = -Ls[i][j3];                    // -E_offdiag (i>j)
        int ks = f >> 4, within = f & 15;
        int hh = within >> 3, bb = within & 1, qq = (within & 7) >> 1;
        int lane = ((k & 7) << 2) | qq;
        int e = (ks * 8 + (k >> 3)) * 32 + lane;
        ((__nv_bfloat16*)d_Wf)[e * 4 + hh * 2 + bb] = __float2bfloat16(w);
    }
}

// ---------------------------------------------------------------------------
// main: 256 CTAs x 128 threads. Per warp: rows wid*32..+31, all 64 comps.
// scores[128,64] = F[128,2176] @ Wf^T via mma.sync bf16 (fp32 acc);
// A-fragments (features) computed in registers; B streamed from L2.
// ---------------------------------------------------------------------------
__global__ __launch_bounds__(128) void gmm_main(const float* __restrict__ x) {
    __shared__ float xs[128][68];      // row: 64 x, [64]=1, [65]=0
    __shared__ float xxs[128];
    __shared__ float gs[K];
    __shared__ int   tab[NF];
    __shared__ float red[128];

    const int tid = threadIdx.x;
    const int wid = tid >> 5, lane = tid & 31;
    const int q = lane & 3, ro = lane >> 2;

    // load sample row, accumulate ||x||^2
    {
        const float4* xg = (const float4*)(x + ((size_t)blockIdx.x * 128 + tid) * D);
        float xx = 0.0f;
        float4* xrow = (float4*)&xs[tid][0];
        #pragma unroll
        for (int i = 0; i < 16; ++i) {
            float4 v = xg[i];
            xrow[i] = v;
            xx = fmaf(v.x, v.x, xx); xx = fmaf(v.y, v.y, xx);
            xx = fmaf(v.z, v.z, xx); xx = fmaf(v.w, v.w, xx);
        }
        xs[tid][64] = 1.0f; xs[tid][65] = 0.0f;
        xxs[tid] = xx;
    }
    for (int f = tid; f < NF; f += 128) tab[f] = d_tab[f];
    if (tid < K) gs[tid] = d_g[tid];
    __syncthreads();

    const int wbase = wid * 32;
    const float* rp0 = &xs[wbase + ro][0];        // mt0 rows
    const float* rp1 = &xs[wbase + ro + 8][0];
    const float* rp2 = &xs[wbase + ro + 16][0];   // mt1 rows
    const float* rp3 = &xs[wbase + ro + 24][0];

    float acc[2][8][4];
    #pragma unroll
    for (int mt = 0; mt < 2; ++mt)
        #pragma unroll
        for (int nt = 0; nt < 8; ++nt)
            #pragma unroll
            for (int c = 0; c < 4; ++c) acc[mt][nt][c] = 0.0f;

    const ull* wf = d_Wf + lane;

    // B double buffer (register)
    ull bb[8];
    #pragma unroll
    for (int nt = 0; nt < 8; ++nt) bb[nt] = wf[nt * 32];

    #pragma unroll 1
    for (int ks = 0; ks < NKS; ++ks) {
        // prefetch next k-step's B fragments
        ull bn[8];
        {
            const int kn = (ks + 1 < NKS) ? ks + 1 : NKS - 1;
            #pragma unroll
            for (int nt = 0; nt < 8; ++nt) bn[nt] = wf[kn * 256 + nt * 32];
        }
        // feature columns for this lane: c0, c0+1, c0+8, c0+9
        const int c0 = ks * 16 + q * 2;
        const int2 tlo = *(const int2*)&tab[c0];
        const int2 thi = *(const int2*)&tab[c0 + 8];
        const int i0 = tlo.x >> 8, j0 = tlo.x & 255;
        const int i1 = tlo.y >> 8, j1 = tlo.y & 255;
        const int i2 = thi.x >> 8, j2 = thi.x & 255;
        const int i3 = thi.y >> 8, j3 = thi.y & 255;

        unsigned a0[4], a1[4];   // [mt][reg]
        a0[0] = cvt_bf16x2(rp0[i0] * rp0[j0], rp0[i1] * rp0[j1]);
        a0[1] = cvt_bf16x2(rp1[i0] * rp1[j0], rp1[i1] * rp1[j1]);
        a0[2] = cvt_bf16x2(rp0[i2] * rp0[j2], rp0[i3] * rp0[j3]);
        a0[3] = cvt_bf16x2(rp1[i2] * rp1[j2], rp1[i3] * rp1[j3]);
        a1[0] = cvt_bf16x2(rp2[i0] * rp2[j0], rp2[i1] * rp2[j1]);
        a1[1] = cvt_bf16x2(rp3[i0] * rp3[j0], rp3[i1] * rp3[j1]);
        a1[2] = cvt_bf16x2(rp2[i2] * rp2[j2], rp2[i3] * rp2[j3]);
        a1[3] = cvt_bf16x2(rp3[i2] * rp3[j2], rp3[i3] * rp3[j3]);

        #pragma unroll
        for (int nt = 0; nt < 8; ++nt) {
            const unsigned b0 = (unsigned)(bb[nt] & 0xFFFFFFFFu);
            const unsigned b1 = (unsigned)(bb[nt] >> 32);
            mma_bf16(acc[0][nt][0], acc[0][nt][1], acc[0][nt][2], acc[0][nt][3],
                     a0[0], a0[1], a0[2], a0[3], b0, b1);
            mma_bf16(acc[1][nt][0], acc[1][nt][1], acc[1][nt][2], acc[1][nt][3],
                     a1[0], a1[1], a1[2], a1[3], b0, b1);
        }
        #pragma unroll
        for (int nt = 0; nt < 8; ++nt) bb[nt] = bn[nt];
    }

    // epilogue: per thread 4 rows x 16 comps; quad-shuffle LSE per row
    float lpsum = 0.0f;
    #pragma unroll
    for (int mt = 0; mt < 2; ++mt) {
        #pragma unroll
        for (int hf = 0; hf < 2; ++hf) {
            const int row = wbase + ro + 16 * mt + 8 * hf;
            const float cxx = -0.5f * xxs[row];
            float v[16];
            float m = -1e30f;
            #pragma unroll
            for (int nt = 0; nt < 8; ++nt) {
                #pragma unroll
                for (int cc = 0; cc < 2; ++cc) {
                    float val = acc[mt][nt][hf * 2 + cc] + gs[nt * 8 + q * 2 + cc] + cxx;
                    v[nt * 2 + cc] = val;
                    m = fmaxf(m, val);
                }
            }
            m = fmaxf(m, __shfl_xor_sync(0xFFFFFFFFu, m, 1));
            m = fmaxf(m, __shfl_xor_sync(0xFFFFFFFFu, m, 2));
            float s = 0.0f;
            #pragma unroll
            for (int u = 0; u < 16; ++u) s += __expf(v[u] - m);
            s += __shfl_xor_sync(0xFFFFFFFFu, s, 1);
            s += __shfl_xor_sync(0xFFFFFFFFu, s, 2);
            lpsum += m + logf(s);
        }
    }
    red[tid] = (q == 0) ? lpsum : 0.0f;
    __syncthreads();
    #pragma unroll
    for (int s = 64; s > 0; s >>= 1) {
        if (tid < s) red[tid] += red[tid + s];
        __syncthreads();
    }
    if (tid == 0) d_partial[blockIdx.x] = red[0];
}

__global__ void finish_kernel(float* __restrict__ out) {
    __shared__ float red[NBLK_MAIN];
    int tid = threadIdx.x;
    red[tid] = d_partial[tid];
    __syncthreads();
    #pragma unroll
    for (int s = NBLK_MAIN / 2; s > 0; s >>= 1) {
        if (tid < s) red[tid] += red[tid + s];
        __syncthreads();
    }
    if (tid == 0) out[0] = -red[0] / (float)BTOT;
}

extern "C" void kernel_launch(void* const* d_in, const int* in_sizes, int n_in,
                              void* d_out, int out_size) {
    const float* x      = (const float*)d_in[0];
    const float* means  = (const float*)d_in[1];
    const float* scale  = (const float*)d_in[2];
    const float* wraw   = (const float*)d_in[3];

    init_tables<<<1, 256>>>();
    prep_kernel<<<K, 128>>>(scale, means, wraw);
    gmm_main<<<NBLK_MAIN, 128>>>(x);
    finish_kernel<<<1, NBLK_MAIN>>>((float*)d_out);
}

// round 12
// speedup vs baseline: 4.2036x; 1.6970x over previous
#include <cuda_runtime.h>
#include <cuda_bf16.h>
#include <math.h>

#define BTOT 32768
#define K 64
#define D 64
#define NF 2176            // padded feature count (136 k-steps of 16)
#define NG 1088            // feature groups of 2
#define NKS 136
#define NBLK_MAIN 256      // 128 samples per CTA

typedef unsigned long long ull;

// ---------------- device scratch (no allocs) ----------------
// B operand in mma.sync fragment-linear layout:
// entry e = (kstep*8 + ntile)*32 + lane, 8 bytes = {b0(lo32), b1(hi32)}
__device__ ull      d_Wf[NKS * 8 * 32];
__device__ float    d_g[K];
__device__ float    d_partial[NBLK_MAIN];
__device__ unsigned d_count = 0;

// ---------------- helpers ----------------
__device__ __forceinline__ ull fma2(ull a, ull b, ull c) {
    ull d; asm("fma.rn.f32x2 %0, %1, %2, %3;" : "=l"(d) : "l"(a), "l"(b), "l"(c)); return d;
}
__device__ __forceinline__ float hadd2(ull a) {
    float lo, hi; asm("mov.b64 {%0, %1}, %2;" : "=f"(lo), "=f"(hi) : "l"(a)); return lo + hi;
}
__device__ __forceinline__ ull pack2(float lo, float hi) {
    ull d; asm("mov.b64 %0, {%1, %2};" : "=l"(d) : "f"(lo), "f"(hi)); return d;
}
__device__ __forceinline__ void lds2(ull& a, ull& b, unsigned addr) {
    asm("ld.shared.v2.b64 {%0, %1}, [%2];" : "=l"(a), "=l"(b) : "r"(addr));
}
// packs: lower 16 bits <- lo, upper <- hi (first PTX src goes to upper half)
__device__ __forceinline__ unsigned cvt_bf16x2(float lo, float hi) {
    unsigned r;
    asm("cvt.rn.satfinite.bf16x2.f32 %0, %1, %2;" : "=r"(r) : "f"(hi), "f"(lo));
    return r;
}
__device__ __forceinline__ void mma_bf16(float& c0, float& c1, float& c2, float& c3,
                                         unsigned a0, unsigned a1, unsigned a2, unsigned a3,
                                         unsigned b0, unsigned b1) {
    asm volatile("mma.sync.aligned.m16n8k16.row.col.f32.bf16.bf16.f32 "
                 "{%0,%1,%2,%3}, {%4,%5,%6,%7}, {%8,%9}, {%0,%1,%2,%3};"
                 : "+f"(c0), "+f"(c1), "+f"(c2), "+f"(c3)
                 : "r"(a0), "r"(a1), "r"(a2), "r"(a3), "r"(b0), "r"(b1));
}

// ---------------------------------------------------------------------------
// Group table (closed form). Group g -> code (i<<8)|j0 meaning feature columns
// 2g = x_i * x_j0, 2g+1 = x_i * x_(j0+1).
//   g < 32:   (64, 2g)  -> linear features (x[64]=1)
//   g >= 32:  lower-tri rows, row i has floor(i/2)+1 groups; j0+1 > i is a
//             pad column (weight 0 in W; feature value irrelevant but finite).
// C(i) = prefix group count: i=2m -> m(m+1); i=2m+1 -> (m+1)^2.
// ---------------------------------------------------------------------------
__device__ __forceinline__ int Cgrp(int t) {
    int m = t >> 1;
    return (t & 1) ? (m + 1) * (m + 1) : m * (m + 1);
}
__device__ __forceinline__ int group_code(int g) {
    if (g < 32) return (64 << 8) | (2 * g);
    int G = g - 32;
    int i = (int)sqrtf(4.0f * (float)G + 1.0f) - 1;
    if (i < 0) i = 0;
    if (i > 63) i = 63;
    while (i < 63 && Cgrp(i + 1) <= G) ++i;
    while (Cgrp(i) > G) --i;
    int j0 = (G - Cgrp(i)) * 2;
    return (i << 8) | j0;
}

// ---------------------------------------------------------------------------
// prep: one 128-thread block per component k.
//   L -> Linv (forward substitution), A = Linv^T Linv, b = A mu, g.
//   Weights written to d_Wf in mma.sync B-fragment layout (bf16).
// ---------------------------------------------------------------------------
__global__ __launch_bounds__(128) void prep_kernel(const float* __restrict__ scale_raw,
                                                   const float* __restrict__ means_raw,
                                                   const float* __restrict__ weights_raw) {
    const int k = blockIdx.x;
    const int tid = threadIdx.x;

    __shared__ float Ls[D][D];     // L; later holds A
    __shared__ float VT[D][68];    // VT[j][i] = Linv[i][j] (16B-aligned stride)
    __shared__ float rdiag[D], ms[D], pdiag[D], bsm[D], wsh[D];
    __shared__ float wstage[K];
    __shared__ float bp2[128];

    const float sc2 = 1.0f / 512.0f;
    const float sc1 = 1.0f / 64.0f;

    for (int idx = tid; idx < D * D; idx += 128) {
        int i = idx >> 6, jj = idx & 63;
        float p = scale_raw[(size_t)k * D * D + idx] * sc2;
        float v;
        if (jj < i) v = p;
        else if (jj == i) { float e = expf(p); v = e; pdiag[i] = p; rdiag[i] = 1.0f / e; }
        else v = 0.0f;
        Ls[i][jj] = v;
    }
    if (tid < D) ms[tid] = means_raw[k * D + tid] * sc1;
    if (tid < K) wstage[tid] = weights_raw[tid] * 0.125f;
    __syncthreads();

    // forward substitution: thread j (<64) computes column j into VT[j][*]
    if (tid < D) {
        const int j = tid;
        float prev = 0.0f;
        #pragma unroll 1
        for (int i = 0; i < D; ++i) {
            const float* Lrow = &Ls[i][0];
            const int e = i - 1;
            const int mend = (e > 0) ? (e & ~3) : 0;
            float a0 = 0.f, a1 = 0.f, a2 = 0.f, a3 = 0.f;
            #pragma unroll 1
            for (int m = 0; m < mend; m += 4) {
                float4 vm = *(const float4*)&VT[j][m];
                a0 = fmaf(Lrow[m + 0], vm.x, a0);
                a1 = fmaf(Lrow[m + 1], vm.y, a1);
                a2 = fmaf(Lrow[m + 2], vm.z, a2);
                a3 = fmaf(Lrow[m + 3], vm.w, a3);
            }
            for (int m = mend; m < e; ++m) a0 = fmaf(Lrow[m], VT[j][m], a0);
            float s = (a0 + a1) + (a2 + a3);
            if (i > 0) s = fmaf(Lrow[e], prev, s);
            float de = (j == i) ? 1.0f : 0.0f;
            float vi = (de - s) * rdiag[i];
            VT[j][i] = vi;
            prev = vi;
        }
    }
    __syncthreads();

    // A rows: thread (jj, h): A[jj][q] for q in [32h, 32h+32)
    const int jj = tid & 63, h = tid >> 6;
    ull vp[32];
    {
        const float4* myrow = (const float4*)&VT[jj][0];
        #pragma unroll
        for (int c = 0; c < 16; ++c) {
            float4 v4 = myrow[c];
            vp[2 * c + 0] = pack2(v4.x, v4.y);
            vp[2 * c + 1] = pack2(v4.z, v4.w);
        }
    }
    float bpart = 0.0f;
    const unsigned vtb = (unsigned)__cvta_generic_to_shared(&VT[0][0]);
    #pragma unroll 2
    for (int qq = 0; qq < 32; ++qq) {
        const int q = h * 32 + qq;
        const unsigned qa = vtb + (unsigned)q * 272u;
        ull acc = 0ULL;
        #pragma unroll
        for (int c = 0; c < 16; ++c) {
            ull w0, w1;
            lds2(w0, w1, qa + 16u * c);
            acc = fma2(w0, vp[2 * c + 0], acc);
            acc = fma2(w1, vp[2 * c + 1], acc);
        }
        float a = hadd2(acc);
        Ls[jj][q] = a;                       // overwrite L with A
        bpart = fmaf(a, ms[q], bpart);
    }
    bp2[tid] = bpart;
    __syncthreads();
    if (tid < D) {
        float bj = bp2[tid] + bp2[tid + 64];
        bsm[tid] = bj;
        wsh[tid] = ms[tid] * bj;             // mu_j * b_j
    }
    __syncthreads();

    if (tid == 0) {
        float hld = 0.0f, c = 0.0f;
        for (int i = 0; i < D; ++i) { hld += pdiag[i]; c += wsh[i]; }
        float wmax = -1e30f;
        for (int q = 0; q < K; ++q) wmax = fmaxf(wmax, wstage[q]);
        float lse = 0.0f;
        for (int q = 0; q < K; ++q) lse += expf(wstage[q] - wmax);
        float logwk = wstage[k] - (wmax + logf(lse));
        const float HALF_D_LOG2PI = 0.5f * 64.0f * 1.8378770664093453f;
        d_g[k] = logwk - hld - HALF_D_LOG2PI - 0.5f * c;
    }

    // W scatter into B-fragment layout (paired-group feature ordering):
    // entry e = (ks*8 + k/8)*32 + lane, lane = 4*(k%8) + (within%8)/2;
    // bf16 slot = (within/8)*2 + (within&1).
    for (int f = tid; f < NF; f += 128) {
        int g = f >> 1, p = f & 1;
        int code = group_code(g);
        int i = code >> 8, j = (code & 255) + p;
        float w;
        if (i == 64)      w = bsm[j];                         // linear: b_j
        else if (j > i)   w = 0.0f;                           // pad
        else if (j == i)  w = -0.5f * (Ls[i][i] - 1.0f);      // -0.5*E_diag
        else              w = -Ls[i][j];                      // -E_offdiag (j<i)
        int ks = f >> 4, within = f & 15;
        int hh = within >> 3, bb2 = within & 1, qq = (within & 7) >> 1;
        int lane = ((k & 7) << 2) | qq;
        int e = (ks * 8 + (k >> 3)) * 32 + lane;
        ((__nv_bfloat16*)d_Wf)[e * 4 + hh * 2 + bb2] = __float2bfloat16(w);
    }
}

// ---------------------------------------------------------------------------
// main: 256 CTAs x 128 threads. Per warp: rows wid*32..+31, all 64 comps.
// scores[128,64] = F[128,2176] @ Wf^T via mma.sync bf16 (fp32 acc).
// Paired groups: per lane & k-step, 2 groups -> 1 scalar + 1 LDS.64 per row
// per group. Last CTA (atomic ticket) folds the final reduction in.
// ---------------------------------------------------------------------------
#define DO_STEP(KS, BARR)                                                     \
    do {                                                                      \
        const int gA = (KS) * 8 + q, gB = gA + 4;                             \
        const int t0 = sgrp[gA], t1 = sgrp[gB];                               \
        const int iA = t0 >> 8, jA = t0 & 255;                                \
        const int iB = t1 >> 8, jB = t1 & 255;                                \
        unsigned a0[4], a1[4];                                                \
        {                                                                     \
            float  sA0 = rp0[iA]; float2 vA0 = *(const float2*)(rp0 + jA);    \
            float  sA1 = rp1[iA]; float2 vA1 = *(const float2*)(rp1 + jA);    \
            float  sB0 = rp0[iB]; float2 vB0 = *(const float2*)(rp0 + jB);    \
            float  sB1 = rp1[iB]; float2 vB1 = *(const float2*)(rp1 + jB);    \
            a0[0] = cvt_bf16x2(sA0 * vA0.x, sA0 * vA0.y);                     \
            a0[1] = cvt_bf16x2(sA1 * vA1.x, sA1 * vA1.y);                     \
            a0[2] = cvt_bf16x2(sB0 * vB0.x, sB0 * vB0.y);                     \
            a0[3] = cvt_bf16x2(sB1 * vB1.x, sB1 * vB1.y);                     \
        }                                                                     \
        {                                                                     \
            float  sA2 = rp2[iA]; float2 vA2 = *(const float2*)(rp2 + jA);    \
            float  sA3 = rp3[iA]; float2 vA3 = *(const float2*)(rp3 + jA);    \
            float  sB2 = rp2[iB]; float2 vB2 = *(const float2*)(rp2 + jB);    \
            float  sB3 = rp3[iB]; float2 vB3 = *(const float2*)(rp3 + jB);    \
            a1[0] = cvt_bf16x2(sA2 * vA2.x, sA2 * vA2.y);                     \
            a1[1] = cvt_bf16x2(sA3 * vA3.x, sA3 * vA3.y);                     \
            a1[2] = cvt_bf16x2(sB2 * vB2.x, sB2 * vB2.y);                     \
            a1[3] = cvt_bf16x2(sB3 * vB3.x, sB3 * vB3.y);                     \
        }                                                                     \
        _Pragma("unroll")                                                     \
        for (int nt = 0; nt < 8; ++nt) {                                      \
            const unsigned b0 = (unsigned)(BARR[nt] & 0xFFFFFFFFu);           \
            const unsigned b1 = (unsigned)(BARR[nt] >> 32);                   \
            mma_bf16(acc[0][nt][0], acc[0][nt][1], acc[0][nt][2], acc[0][nt][3], \
                     a0[0], a0[1], a0[2], a0[3], b0, b1);                     \
            mma_bf16(acc[1][nt][0], acc[1][nt][1], acc[1][nt][2], acc[1][nt][3], \
                     a1[0], a1[1], a1[2], a1[3], b0, b1);                     \
        }                                                                     \
    } while (0)

__global__ __launch_bounds__(128) void gmm_main(const float* __restrict__ x,
                                                float* __restrict__ out) {
    __shared__ float xs[128][68];      // row: 64 x values, [64]=1
    __shared__ float xxs[128];
    __shared__ float gs[K];
    __shared__ int   sgrp[NG];
    __shared__ float red[128];
    __shared__ unsigned sflag;

    const int tid = threadIdx.x;
    const int wid = tid >> 5, lane = tid & 31;
    const int q = lane & 3, ro = lane >> 2;

    // group table (closed form, no global table needed)
    for (int g = tid; g < NG; g += 128) sgrp[g] = group_code(g);

    // load sample row, accumulate ||x||^2
    {
        const float4* xg = (const float4*)(x + ((size_t)blockIdx.x * 128 + tid) * D);
        float xx = 0.0f;
        float4* xrow = (float4*)&xs[tid][0];
        #pragma unroll
        for (int i = 0; i < 16; ++i) {
            float4 v = xg[i];
            xrow[i] = v;
            xx = fmaf(v.x, v.x, xx); xx = fmaf(v.y, v.y, xx);
            xx = fmaf(v.z, v.z, xx); xx = fmaf(v.w, v.w, xx);
        }
        xs[tid][64] = 1.0f; xs[tid][65] = 0.0f;
        xxs[tid] = xx;
    }
    if (tid < K) gs[tid] = d_g[tid];
    __syncthreads();

    const int wbase = wid * 32;
    const float* rp0 = &xs[wbase + ro][0];        // mt0 rows
    const float* rp1 = &xs[wbase + ro + 8][0];
    const float* rp2 = &xs[wbase + ro + 16][0];   // mt1 rows
    const float* rp3 = &xs[wbase + ro + 24][0];

    float acc[2][8][4];
    #pragma unroll
    for (int mt = 0; mt < 2; ++mt)
        #pragma unroll
        for (int nt = 0; nt < 8; ++nt)
            #pragma unroll
            for (int c = 0; c < 4; ++c) acc[mt][nt][c] = 0.0f;

    const ull* wf = d_Wf + lane;

    // B double buffer, unroll-2 rotation (no copies)
    ull bA[8], bB[8];
    #pragma unroll
    for (int nt = 0; nt < 8; ++nt) bA[nt] = wf[nt * 32];

    #pragma unroll 1
    for (int ks = 0; ks < NKS; ks += 2) {
        #pragma unroll
        for (int nt = 0; nt < 8; ++nt) bB[nt] = wf[(ks + 1) * 256 + nt * 32];
        DO_STEP(ks, bA);
        const int k2 = (ks + 2 < NKS) ? ks + 2 : NKS - 1;
        #pragma unroll
        for (int nt = 0; nt < 8; ++nt) bA[nt] = wf[k2 * 256 + nt * 32];
        DO_STEP(ks + 1, bB);
    }

    // epilogue: per thread 4 rows x 16 comps; quad-shuffle LSE per row
    float lpsum = 0.0f;
    #pragma unroll
    for (int mt = 0; mt < 2; ++mt) {
        #pragma unroll
        for (int hf = 0; hf < 2; ++hf) {
            const int row = wbase + ro + 16 * mt + 8 * hf;
            const float cxx = -0.5f * xxs[row];
            float v[16];
            float m = -1e30f;
            #pragma unroll
            for (int nt = 0; nt < 8; ++nt) {
                #pragma unroll
                for (int cc = 0; cc < 2; ++cc) {
                    float val = acc[mt][nt][hf * 2 + cc] + gs[nt * 8 + q * 2 + cc] + cxx;
                    v[nt * 2 + cc] = val;
                    m = fmaxf(m, val);
                }
            }
            m = fmaxf(m, __shfl_xor_sync(0xFFFFFFFFu, m, 1));
            m = fmaxf(m, __shfl_xor_sync(0xFFFFFFFFu, m, 2));
            float s = 0.0f;
            #pragma unroll
            for (int u = 0; u < 16; ++u) s += __expf(v[u] - m);
            s += __shfl_xor_sync(0xFFFFFFFFu, s, 1);
            s += __shfl_xor_sync(0xFFFFFFFFu, s, 2);
            lpsum += m + logf(s);
        }
    }
    red[tid] = (q == 0) ? lpsum : 0.0f;
    __syncthreads();
    #pragma unroll
    for (int s = 64; s > 0; s >>= 1) {
        if (tid < s) red[tid] += red[tid + s];
        __syncthreads();
    }
    if (tid == 0) {
        d_partial[blockIdx.x] = red[0];
        __threadfence();
        unsigned ticket = atomicAdd(&d_count, 1u);
        sflag = (ticket == (unsigned)(NBLK_MAIN - 1)) ? 1u : 0u;
    }
    __syncthreads();

    // last CTA: final deterministic reduction + counter reset
    if (sflag) {
        __threadfence();
        float s2 = d_partial[tid] + d_partial[tid + 128];
        red[tid] = s2;
        __syncthreads();
        #pragma unroll
        for (int s = 64; s > 0; s >>= 1) {
            if (tid < s) red[tid] += red[tid + s];
            __syncthreads();
        }
        if (tid == 0) {
            out[0] = -red[0] / (float)BTOT;
            d_count = 0;                      // reset for next graph replay
        }
    }
}

extern "C" void kernel_launch(void* const* d_in, const int* in_sizes, int n_in,
                              void* d_out, int out_size) {
    const float* x      = (const float*)d_in[0];
    const float* means  = (const float*)d_in[1];
    const float* scale  = (const float*)d_in[2];
    const float* wraw   = (const float*)d_in[3];

    prep_kernel<<<K, 128>>>(scale, means, wraw);
    gmm_main<<<NBLK_MAIN, 128>>>(x, (float*)d_out);
}